// round 1
// baseline (speedup 1.0000x reference)
#include <cuda_runtime.h>
#include <math.h>

#define N_PTS 8192
#define KMASK 0xFFFFE000u
#define IDXMASK 8191u

#define TPT 16           // targets per thread (register resident)
#define BT 256           // threads per block
#define TGT_TILE (TPT*BT)   // 4096 targets per block
#define TGT_CHUNKS (N_PTS/TGT_TILE)  // 2
#define SRC_TILE 32
#define SRC_CHUNKS (N_PTS/SRC_TILE)  // 256

__device__ float g_R[9];
__device__ float4 g_src4[N_PTS];   // transformed source points, w = -0.5*||s||^2
__device__ float4 g_tgt4[N_PTS];   // target points, w = -0.5*||t||^2
__device__ float4 g_srcn[N_PTS];   // rotated source normals, w = norm
__device__ unsigned g_rowmin[N_PTS];
__device__ unsigned g_colmin[N_PTS];

// ---------------------------------------------------------------------------
// Kernel 0: 6d -> rotation matrix (single thread)
// ---------------------------------------------------------------------------
__global__ void k_rot(const float* __restrict__ r6) {
    float a1x = r6[0], a1y = r6[1], a1z = r6[2];
    float a2x = r6[3], a2y = r6[4], a2z = r6[5];
    float n1 = sqrtf(a1x*a1x + a1y*a1y + a1z*a1z);
    float b1x = a1x/n1, b1y = a1y/n1, b1z = a1z/n1;
    float d = b1x*a2x + b1y*a2y + b1z*a2z;
    float c2x = a2x - d*b1x, c2y = a2y - d*b1y, c2z = a2z - d*b1z;
    float n2 = sqrtf(c2x*c2x + c2y*c2y + c2z*c2z);
    float b2x = c2x/n2, b2y = c2y/n2, b2z = c2z/n2;
    float b3x = b1y*b2z - b1z*b2y;
    float b3y = b1z*b2x - b1x*b2z;
    float b3z = b1x*b2y - b1y*b2x;
    // R = [b1 b2 b3] as columns, stored row-major
    g_R[0] = b1x; g_R[1] = b2x; g_R[2] = b3x;
    g_R[3] = b1y; g_R[4] = b2y; g_R[5] = b3y;
    g_R[6] = b1z; g_R[7] = b2z; g_R[8] = b3z;
}

// ---------------------------------------------------------------------------
// Kernel 1: transform sources/normals, precompute ht for targets, init mins
// ---------------------------------------------------------------------------
__global__ void k_prep(const float* __restrict__ sp, const float* __restrict__ tp,
                       const float* __restrict__ sn, const float* __restrict__ tr,
                       const float* __restrict__ sc) {
    int i = blockIdx.x * blockDim.x + threadIdx.x;
    if (i >= N_PTS) return;
    float R0 = g_R[0], R1 = g_R[1], R2 = g_R[2];
    float R3 = g_R[3], R4 = g_R[4], R5 = g_R[5];
    float R6 = g_R[6], R7 = g_R[7], R8 = g_R[8];
    float t0 = tr[0], t1 = tr[1], t2 = tr[2];
    float s0 = sc[0], s1 = sc[1], s2 = sc[2];

    float px = sp[3*i+0] * s0, py = sp[3*i+1] * s1, pz = sp[3*i+2] * s2;
    float vx = R0*px + R1*py + R2*pz + t0;
    float vy = R3*px + R4*py + R5*pz + t1;
    float vz = R6*px + R7*py + R8*pz + t2;
    float hs = -0.5f * (vx*vx + vy*vy + vz*vz);
    g_src4[i] = make_float4(vx, vy, vz, hs);

    float nx = sn[3*i+0], ny = sn[3*i+1], nz = sn[3*i+2];
    float wx = R0*nx + R1*ny + R2*nz;
    float wy = R3*nx + R4*ny + R5*nz;
    float wz = R6*nx + R7*ny + R8*nz;
    float wn = sqrtf(wx*wx + wy*wy + wz*wz);
    g_srcn[i] = make_float4(wx, wy, wz, wn);

    float tx = tp[3*i+0], ty = tp[3*i+1], tz = tp[3*i+2];
    float ht = -0.5f * (tx*tx + ty*ty + tz*tz);
    g_tgt4[i] = make_float4(tx, ty, tz, ht);

    g_rowmin[i] = 0xFFFFFFFFu;
    g_colmin[i] = 0xFFFFFFFFu;
}

// ---------------------------------------------------------------------------
// Kernel 2: fused pair pass. m = hs + ht + dot(s,t) = -d2/2 <= 0.
// For negative floats: smaller d2 <=> larger m <=> smaller uint bits.
// key = (bits(m) & 0xFFFFE000) | idx  -> umin gives min+argmin in one word.
// ---------------------------------------------------------------------------
__global__ void __launch_bounds__(BT, 2) k_pairs() {
    const int tchunk = blockIdx.x;           // 0..TGT_CHUNKS-1
    const int schunk = blockIdx.y;           // 0..SRC_CHUNKS-1
    const int tid = threadIdx.x;

    __shared__ float4 ssrc[SRC_TILE];

    // Register-resident targets (coalesced: stride BT)
    float4 T[TPT];
    unsigned ck[TPT];
    int tg[TPT];
    const int tbase = tchunk * TGT_TILE + tid;
#pragma unroll
    for (int u = 0; u < TPT; u++) {
        tg[u] = tbase + u * BT;
        T[u]  = g_tgt4[tg[u]];
        ck[u] = 0xFFFFFFFFu;
    }

    const int sbase = schunk * SRC_TILE;
    if (tid < SRC_TILE) ssrc[tid] = g_src4[sbase + tid];
    __syncthreads();

    for (int s = 0; s < SRC_TILE; s++) {
        float4 S = ssrc[s];
        unsigned skey = (unsigned)(sbase + s);
        unsigned rloc = 0xFFFFFFFFu;
#pragma unroll
        for (int u = 0; u < TPT; u++) {
            float m = fmaf(T[u].z, S.z, fmaf(T[u].y, S.y, fmaf(T[u].x, S.x, S.w + T[u].w)));
            unsigned b = __float_as_uint(m);
            unsigned krow = (b & KMASK) | (unsigned)tg[u];
            unsigned kcol = (b & KMASK) | skey;
            rloc  = umin(rloc, krow);
            ck[u] = umin(ck[u], kcol);
        }
        // warp-level row-min reduce, one global atomic per warp
#pragma unroll
        for (int off = 16; off; off >>= 1)
            rloc = umin(rloc, __shfl_xor_sync(0xFFFFFFFFu, rloc, off));
        if ((tid & 31) == 0) atomicMin(&g_rowmin[sbase + s], rloc);
    }

#pragma unroll
    for (int u = 0; u < TPT; u++)
        atomicMin(&g_colmin[tg[u]], ck[u]);
}

// ---------------------------------------------------------------------------
// Kernel 3: exact epilogue. Recompute distances & normal terms from the
// winning indices, deterministic block-tree reduction, write scalar loss.
// ---------------------------------------------------------------------------
__global__ void k_final(const float* __restrict__ tn, float* __restrict__ out) {
    const int tid = threadIdx.x;
    const int NT = 1024;
    const float EPS = 1e-6f;
    __shared__ float sh[NT];

    float sd_s = 0.f, sd_t = 0.f, sc_s = 0.f, sc_t = 0.f;

    for (int i = tid; i < N_PTS; i += NT) {
        // source -> target
        {
            int j = (int)(g_rowmin[i] & IDXMASK);
            float4 S = g_src4[i];
            float4 T = g_tgt4[j];
            float ns = S.x*S.x + S.y*S.y + S.z*S.z;
            float nt2 = T.x*T.x + T.y*T.y + T.z*T.z;
            float dp = S.x*T.x + S.y*T.y + S.z*T.z;
            float d2 = fmaxf(ns + nt2 - 2.f*dp, 0.f);
            sd_s += d2;

            float4 Nn = g_srcn[i];
            float ax = tn[3*j+0], ay = tn[3*j+1], az = tn[3*j+2];
            float an = sqrtf(ax*ax + ay*ay + az*az);
            float cs = (Nn.x*ax + Nn.y*ay + Nn.z*az) /
                       (fmaxf(Nn.w, EPS) * fmaxf(an, EPS));
            sc_s += 1.f - fabsf(cs);
        }
        // target -> source
        {
            int j = (int)(g_colmin[i] & IDXMASK);
            float4 T = g_tgt4[i];
            float4 S = g_src4[j];
            float ns = S.x*S.x + S.y*S.y + S.z*S.z;
            float nt2 = T.x*T.x + T.y*T.y + T.z*T.z;
            float dp = S.x*T.x + S.y*T.y + S.z*T.z;
            float d2 = fmaxf(ns + nt2 - 2.f*dp, 0.f);
            sd_t += d2;

            float ax = tn[3*i+0], ay = tn[3*i+1], az = tn[3*i+2];
            float an = sqrtf(ax*ax + ay*ay + az*az);
            float4 Sn = g_srcn[j];
            float cs = (ax*Sn.x + ay*Sn.y + az*Sn.z) /
                       (fmaxf(an, EPS) * fmaxf(Sn.w, EPS));
            sc_t += 1.f - fabsf(cs);
        }
    }

    // deterministic tree reductions
    float vals[4] = {sd_s, sd_t, sc_s, sc_t};
    float tot[4];
#pragma unroll
    for (int k = 0; k < 4; k++) {
        sh[tid] = vals[k];
        __syncthreads();
        for (int off = NT/2; off; off >>= 1) {
            if (tid < off) sh[tid] += sh[tid + off];
            __syncthreads();
        }
        tot[k] = sh[0];
        __syncthreads();
    }

    if (tid == 0) {
        const float invN = 1.0f / (float)N_PTS;
        float loss = tot[0]*invN + tot[1]*invN + 0.1f*(tot[2]*invN + tot[3]*invN);
        out[0] = loss;
    }
}

// ---------------------------------------------------------------------------
extern "C" void kernel_launch(void* const* d_in, const int* in_sizes, int n_in,
                              void* d_out, int out_size) {
    const float* sp = (const float*)d_in[0];  // source_points   [8192,3]
    const float* tp = (const float*)d_in[1];  // target_points   [8192,3]
    const float* sn = (const float*)d_in[2];  // source_normals  [8192,3]
    const float* tn = (const float*)d_in[3];  // target_normals  [8192,3]
    const float* tr = (const float*)d_in[4];  // translation     [3]
    const float* r6 = (const float*)d_in[5];  // rotation_6d     [6]
    const float* sc = (const float*)d_in[6];  // scale           [3]
    float* out = (float*)d_out;

    k_rot<<<1, 1>>>(r6);
    k_prep<<<(N_PTS + 255) / 256, 256>>>(sp, tp, sn, tr, sc);
    dim3 grid(TGT_CHUNKS, SRC_CHUNKS);
    k_pairs<<<grid, BT>>>();
    k_final<<<1, 1024>>>(tn, out);
}

// round 2
// speedup vs baseline: 1.4942x; 1.4942x over previous
#include <cuda_runtime.h>
#include <math.h>

#define N_PTS 8192
#define KMASK 0xFFFFE000u
#define IDXMASK 8191u

#define TPT 16                        // targets per thread (register resident)
#define BT 256                        // threads per block
#define TGT_TILE (TPT*BT)             // 4096
#define TGT_CHUNKS (N_PTS/TGT_TILE)   // 2
#define SRC_TILE 64
#define SRC_CHUNKS (N_PTS/SRC_TILE)   // 128  -> grid 256 blocks = 1 wave @ occ2
#define FB 32                         // epilogue blocks

__device__ float4 g_src4[N_PTS];      // transformed source, w = -0.5*||s||^2
__device__ float4 g_tgt4[N_PTS];      // target, w = -0.5*||t||^2
__device__ float4 g_srcn[N_PTS];      // rotated source normal, w = norm
__device__ unsigned g_rowmin[N_PTS];
__device__ unsigned g_colmin[N_PTS];
__device__ float g_part[FB][4];

// ---- packed f32x2 helpers (Blackwell FFMA2/FADD2) -------------------------
__device__ __forceinline__ unsigned long long pk2(float lo, float hi) {
    unsigned long long d;
    asm("mov.b64 %0,{%1,%2};" : "=l"(d) : "f"(lo), "f"(hi));
    return d;
}
__device__ __forceinline__ unsigned long long add2(unsigned long long a, unsigned long long b) {
    unsigned long long d;
    asm("add.rn.f32x2 %0,%1,%2;" : "=l"(d) : "l"(a), "l"(b));
    return d;
}
__device__ __forceinline__ unsigned long long fma2(unsigned long long a, unsigned long long b, unsigned long long c) {
    unsigned long long d;
    asm("fma.rn.f32x2 %0,%1,%2,%3;" : "=l"(d) : "l"(a), "l"(b), "l"(c));
    return d;
}
__device__ __forceinline__ void upk(unsigned long long d, unsigned& lo, unsigned& hi) {
    asm("mov.b64 {%0,%1},%2;" : "=r"(lo), "=r"(hi) : "l"(d));
}

// ---------------------------------------------------------------------------
// Kernel 1: transform sources/normals (R computed per-thread, trivial),
// precompute target halves, init min arrays.
// ---------------------------------------------------------------------------
__global__ void k_prep(const float* __restrict__ sp, const float* __restrict__ tp,
                       const float* __restrict__ sn, const float* __restrict__ tr,
                       const float* __restrict__ sc, const float* __restrict__ r6) {
    int i = blockIdx.x * blockDim.x + threadIdx.x;
    if (i >= N_PTS) return;

    // rotation_6d -> R (redundant per thread; ~80 flops)
    float a1x = r6[0], a1y = r6[1], a1z = r6[2];
    float a2x = r6[3], a2y = r6[4], a2z = r6[5];
    float n1 = sqrtf(a1x*a1x + a1y*a1y + a1z*a1z);
    float b1x = a1x/n1, b1y = a1y/n1, b1z = a1z/n1;
    float dd = b1x*a2x + b1y*a2y + b1z*a2z;
    float c2x = a2x - dd*b1x, c2y = a2y - dd*b1y, c2z = a2z - dd*b1z;
    float n2 = sqrtf(c2x*c2x + c2y*c2y + c2z*c2z);
    float b2x = c2x/n2, b2y = c2y/n2, b2z = c2z/n2;
    float b3x = b1y*b2z - b1z*b2y;
    float b3y = b1z*b2x - b1x*b2z;
    float b3z = b1x*b2y - b1y*b2x;
    // R rows (R = [b1 b2 b3] columns)
    float R0 = b1x, R1 = b2x, R2 = b3x;
    float R3 = b1y, R4 = b2y, R5 = b3y;
    float R6 = b1z, R7 = b2z, R8 = b3z;

    float t0 = tr[0], t1 = tr[1], t2 = tr[2];
    float s0 = sc[0], s1 = sc[1], s2 = sc[2];

    float px = sp[3*i+0] * s0, py = sp[3*i+1] * s1, pz = sp[3*i+2] * s2;
    float vx = R0*px + R1*py + R2*pz + t0;
    float vy = R3*px + R4*py + R5*pz + t1;
    float vz = R6*px + R7*py + R8*pz + t2;
    float hs = -0.5f * (vx*vx + vy*vy + vz*vz);
    g_src4[i] = make_float4(vx, vy, vz, hs);

    float nx = sn[3*i+0], ny = sn[3*i+1], nz = sn[3*i+2];
    float wx = R0*nx + R1*ny + R2*nz;
    float wy = R3*nx + R4*ny + R5*nz;
    float wz = R6*nx + R7*ny + R8*nz;
    float wn = sqrtf(wx*wx + wy*wy + wz*wz);
    g_srcn[i] = make_float4(wx, wy, wz, wn);

    float tx = tp[3*i+0], ty = tp[3*i+1], tz = tp[3*i+2];
    float ht = -0.5f * (tx*tx + ty*ty + tz*tz);
    g_tgt4[i] = make_float4(tx, ty, tz, ht);

    g_rowmin[i] = 0xFFFFFFFFu;
    g_colmin[i] = 0xFFFFFFFFu;
}

// ---------------------------------------------------------------------------
// Kernel 2: fused pair pass, f32x2-packed. m = hs + ht + dot(s,t) = -d2/2 <= 0.
// For negative floats: smaller d2 <=> larger m <=> smaller uint bits.
// key = (bits(m) & KMASK) | idx -> umin does min+argmin in one word.
// ---------------------------------------------------------------------------
__global__ void __launch_bounds__(BT, 2) k_pairs() {
    const int tchunk = blockIdx.x;          // 0..1
    const int schunk = blockIdx.y;          // 0..127
    const int tid = threadIdx.x;

    __shared__ float4 ssrc[SRC_TILE];

    // Register-resident targets, packed pairwise (u=2p lo, u=2p+1 hi)
    unsigned long long Tx[TPT/2], Ty[TPT/2], Tz[TPT/2], Tw[TPT/2];
    unsigned ck[TPT];
    unsigned cu[TPT];                       // target indices
    const int tbase = tchunk * TGT_TILE + tid;
#pragma unroll
    for (int p = 0; p < TPT/2; p++) {
        float4 a = g_tgt4[tbase + (2*p)   * BT];
        float4 b = g_tgt4[tbase + (2*p+1) * BT];
        Tx[p] = pk2(a.x, b.x);
        Ty[p] = pk2(a.y, b.y);
        Tz[p] = pk2(a.z, b.z);
        Tw[p] = pk2(a.w, b.w);
    }
#pragma unroll
    for (int u = 0; u < TPT; u++) {
        ck[u] = 0xFFFFFFFFu;
        cu[u] = (unsigned)(tbase + u * BT);
    }

    const int sbase = schunk * SRC_TILE;
    if (tid < SRC_TILE) ssrc[tid] = g_src4[sbase + tid];
    __syncthreads();

    for (int s = 0; s < SRC_TILE; s++) {
        float4 S = ssrc[s];
        unsigned long long Sx = pk2(S.x, S.x);
        unsigned long long Sy = pk2(S.y, S.y);
        unsigned long long Sz = pk2(S.z, S.z);
        unsigned long long Sw = pk2(S.w, S.w);
        const unsigned skey = (unsigned)(sbase + s);
        unsigned rloc = 0xFFFFFFFFu;
#pragma unroll
        for (int p = 0; p < TPT/2; p++) {
            unsigned long long acc = add2(Tw[p], Sw);
            acc = fma2(Tx[p], Sx, acc);
            acc = fma2(Ty[p], Sy, acc);
            acc = fma2(Tz[p], Sz, acc);
            unsigned b0, b1;
            upk(acc, b0, b1);
            rloc        = umin(rloc,        (b0 & KMASK) | cu[2*p]);
            rloc        = umin(rloc,        (b1 & KMASK) | cu[2*p+1]);
            ck[2*p]     = umin(ck[2*p],     (b0 & KMASK) | skey);
            ck[2*p+1]   = umin(ck[2*p+1],   (b1 & KMASK) | skey);
        }
        // warp row-min reduce, one global atomic per warp per s
#pragma unroll
        for (int off = 16; off; off >>= 1)
            rloc = umin(rloc, __shfl_xor_sync(0xFFFFFFFFu, rloc, off));
        if ((tid & 31) == 0) atomicMin(&g_rowmin[sbase + s], rloc);
    }

#pragma unroll
    for (int u = 0; u < TPT; u++)
        atomicMin(&g_colmin[cu[u]], ck[u]);
}

// ---------------------------------------------------------------------------
// Kernel 3a: parallel exact epilogue. 32 blocks x 256 threads = 1 thread/point.
// Recompute distances & normal terms from winning indices; deterministic
// per-block tree reduction into g_part.
// ---------------------------------------------------------------------------
__global__ void k_final1(const float* __restrict__ tn) {
    const int tid = threadIdx.x;
    const int i = blockIdx.x * BT + tid;
    const float EPS = 1e-6f;

    float v0, v1, v2, v3;
    {
        // source -> target
        int j = (int)(g_rowmin[i] & IDXMASK);
        float4 S = g_src4[i];
        float4 T = g_tgt4[j];
        float ns  = S.x*S.x + S.y*S.y + S.z*S.z;
        float nt2 = T.x*T.x + T.y*T.y + T.z*T.z;
        float dp  = S.x*T.x + S.y*T.y + S.z*T.z;
        v0 = fmaxf(ns + nt2 - 2.f*dp, 0.f);

        float4 Nn = g_srcn[i];
        float ax = tn[3*j+0], ay = tn[3*j+1], az = tn[3*j+2];
        float an = sqrtf(ax*ax + ay*ay + az*az);
        float cs = (Nn.x*ax + Nn.y*ay + Nn.z*az) /
                   (fmaxf(Nn.w, EPS) * fmaxf(an, EPS));
        v2 = 1.f - fabsf(cs);
    }
    {
        // target -> source
        int j = (int)(g_colmin[i] & IDXMASK);
        float4 T = g_tgt4[i];
        float4 S = g_src4[j];
        float ns  = S.x*S.x + S.y*S.y + S.z*S.z;
        float nt2 = T.x*T.x + T.y*T.y + T.z*T.z;
        float dp  = S.x*T.x + S.y*T.y + S.z*T.z;
        v1 = fmaxf(ns + nt2 - 2.f*dp, 0.f);

        float ax = tn[3*i+0], ay = tn[3*i+1], az = tn[3*i+2];
        float an = sqrtf(ax*ax + ay*ay + az*az);
        float4 Sn = g_srcn[j];
        float cs = (ax*Sn.x + ay*Sn.y + az*Sn.z) /
                   (fmaxf(an, EPS) * fmaxf(Sn.w, EPS));
        v3 = 1.f - fabsf(cs);
    }

    // deterministic reduction: warp shuffle tree, then fixed-order warp sums
    float v[4] = {v0, v1, v2, v3};
#pragma unroll
    for (int k = 0; k < 4; k++)
#pragma unroll
        for (int off = 16; off; off >>= 1)
            v[k] += __shfl_xor_sync(0xFFFFFFFFu, v[k], off);

    __shared__ float sh[8][4];
    const int warp = tid >> 5;
    if ((tid & 31) == 0) {
        sh[warp][0] = v[0]; sh[warp][1] = v[1];
        sh[warp][2] = v[2]; sh[warp][3] = v[3];
    }
    __syncthreads();
    if (tid == 0) {
#pragma unroll
        for (int k = 0; k < 4; k++) {
            float p = 0.f;
#pragma unroll
            for (int w = 0; w < 8; w++) p += sh[w][k];
            g_part[blockIdx.x][k] = p;
        }
    }
}

// ---------------------------------------------------------------------------
// Kernel 3b: finish — deterministic tree over 32 block partials, write loss.
// ---------------------------------------------------------------------------
__global__ void k_finish(float* __restrict__ out) {
    const int t = threadIdx.x;   // 32 threads
    float v[4];
#pragma unroll
    for (int k = 0; k < 4; k++) v[k] = g_part[t][k];
#pragma unroll
    for (int k = 0; k < 4; k++)
#pragma unroll
        for (int off = 16; off; off >>= 1)
            v[k] += __shfl_xor_sync(0xFFFFFFFFu, v[k], off);
    if (t == 0) {
        const float invN = 1.0f / (float)N_PTS;
        out[0] = v[0]*invN + v[1]*invN + 0.1f*(v[2]*invN + v[3]*invN);
    }
}

// ---------------------------------------------------------------------------
extern "C" void kernel_launch(void* const* d_in, const int* in_sizes, int n_in,
                              void* d_out, int out_size) {
    const float* sp = (const float*)d_in[0];  // source_points   [8192,3]
    const float* tp = (const float*)d_in[1];  // target_points   [8192,3]
    const float* sn = (const float*)d_in[2];  // source_normals  [8192,3]
    const float* tn = (const float*)d_in[3];  // target_normals  [8192,3]
    const float* tr = (const float*)d_in[4];  // translation     [3]
    const float* r6 = (const float*)d_in[5];  // rotation_6d     [6]
    const float* sc = (const float*)d_in[6];  // scale           [3]
    float* out = (float*)d_out;

    k_prep<<<(N_PTS + 255) / 256, 256>>>(sp, tp, sn, tr, sc, r6);
    dim3 grid(TGT_CHUNKS, SRC_CHUNKS);
    k_pairs<<<grid, BT>>>();
    k_final1<<<FB, BT>>>(tn);
    k_finish<<<1, 32>>>(out);
}